// round 9
// baseline (speedup 1.0000x reference)
#include <cuda_runtime.h>
#include <cuda_bf16.h>
#include <cstdint>

#define Bq 32
#define Sq 256
#define Eq 256
#define Hq 512
#define Gq 2048          // 4*H
#define M_TOT (Bq * Sq)  // 8192

#define SCAN_NCTA 128
#define SCAN_TPB  256
#define HP 132           // hsh row pad (floats)
#define WS 516           // Wsh row stride (floats)

#define SCAN_SMEM_FLOATS (64 * WS + 8 * HP + 8 * 64 * 9 + 128)
#define SCAN_SMEM_BYTES  (SCAN_SMEM_FLOATS * 4)

typedef unsigned long long ull;

#define FMA2(acc, a, b) \
    asm("fma.rn.f32x2 %0, %1, %2, %0;" : "+l"(acc) : "l"(a), "l"(b))
#define UNPK2(lo, hi, v) \
    asm("mov.b64 {%0, %1}, %2;" : "=f"(lo), "=f"(hi) : "l"(v))

#define LDMX4(r0, r1, r2, r3, addr) \
    asm volatile("ldmatrix.sync.aligned.m8n8.x4.shared.b16 {%0,%1,%2,%3}, [%4];" \
        : "=r"(r0), "=r"(r1), "=r"(r2), "=r"(r3) : "r"(addr))
#define LDMX2(r0, r1, addr) \
    asm volatile("ldmatrix.sync.aligned.m8n8.x2.shared.b16 {%0,%1}, [%2];" \
        : "=r"(r0), "=r"(r1) : "r"(addr))
#define MMA_BF16(d, a, b0, b1) \
    asm volatile("mma.sync.aligned.m16n8k16.row.col.f32.bf16.bf16.f32 " \
        "{%0,%1,%2,%3}, {%4,%5,%6,%7}, {%8,%9}, {%0,%1,%2,%3};" \
        : "+f"(d[0]), "+f"(d[1]), "+f"(d[2]), "+f"(d[3]) \
        : "r"(a[0]), "r"(a[1]), "r"(a[2]), "r"(a[3]), "r"(b0), "r"(b1))

__device__ __forceinline__ float fsigmoid(float x) {
    return __fdividef(1.f, 1.f + __expf(-x));
}
__device__ __forceinline__ float ftanh(float x) {
    float e = __expf(2.f * x);
    return 1.f - __fdividef(2.f, e + 1.f);
}

// ---------------- device scratch (static, no allocation) ----------------
__device__ float g_gx[M_TOT * Gq];
__device__ float g_io0[M_TOT * Hq];
__device__ float g_io1[M_TOT * Hq];
__device__ float g_h[2][Bq * Hq];
__device__ unsigned g_flags[2][SCAN_NCTA * 32];

// =================== bf16x3 tensor-core input GEMM =======================
// C[m][n] = A[m][:K] . W[n][:K] + bih[n] + bhh[n]
// A = Ahi+Alo (bf16), W = Whi+Wlo; D = AhiWhi + AhiWlo + AloWhi (fp32 acc).
// CTA tile 128x128, 8 warps of 64x32, k-step 16, double-buffered SMEM.
#define GS 24            // SMEM row stride in bf16 (48B: 16B-aligned, bank-free)
#define GBUF (128 * GS)  // one array buffer, bf16 elements

__device__ __forceinline__ void split_store(__nv_bfloat16* hi, __nv_bfloat16* lo,
                                            int eoff, float4 v)
{
    __nv_bfloat162 h01 = __floats2bfloat162_rn(v.x, v.y);
    __nv_bfloat162 h23 = __floats2bfloat162_rn(v.z, v.w);
    float2 f01 = __bfloat1622float2(h01);
    float2 f23 = __bfloat1622float2(h23);
    __nv_bfloat162 l01 = __floats2bfloat162_rn(v.x - f01.x, v.y - f01.y);
    __nv_bfloat162 l23 = __floats2bfloat162_rn(v.z - f23.x, v.w - f23.y);
    uint2 ph, pl;
    ph.x = *reinterpret_cast<unsigned*>(&h01);
    ph.y = *reinterpret_cast<unsigned*>(&h23);
    pl.x = *reinterpret_cast<unsigned*>(&l01);
    pl.y = *reinterpret_cast<unsigned*>(&l23);
    *reinterpret_cast<uint2*>(hi + eoff) = ph;
    *reinterpret_cast<uint2*>(lo + eoff) = pl;
}

__global__ void __launch_bounds__(256, 2) gemm_kernel(
    const float* __restrict__ A, const float* __restrict__ W,
    const float* __restrict__ bih, const float* __restrict__ bhh,
    float* __restrict__ C, int K)
{
    extern __shared__ __nv_bfloat16 gsm[];
    __nv_bfloat16* Ahi = gsm;                 // [2][GBUF]
    __nv_bfloat16* Alo = gsm + 2 * GBUF;
    __nv_bfloat16* Whi = gsm + 4 * GBUF;
    __nv_bfloat16* Wlo = gsm + 6 * GBUF;

    const int tid = threadIdx.x;
    const int m0 = blockIdx.y * 128;
    const int n0 = blockIdx.x * 128;
    const int w = tid >> 5, l = tid & 31;
    const int wm = (w >> 2) * 64;
    const int wn = (w & 3) * 32;

    // loader mapping: idx = i*256+tid -> (row, kq): 4 consecutive tids = one row slice
    const int row0 = tid >> 2, kq0 = tid & 3;            // i = 0
    const int row1 = (256 + tid) >> 2, kq1 = tid & 3;    // i = 1

    // ldmatrix per-lane element offsets (within one buffer array)
    const int tA = l >> 3, rA = l & 7;
    const int aoff = (wm + (tA & 1) * 8 + rA) * GS + (tA >> 1) * 8;
    const int tB = (l >> 3) & 1, rB = l & 7;
    const int boff = (wn + rB) * GS + tB * 8;

    unsigned sbase = (unsigned)__cvta_generic_to_shared(gsm);

    float d[4][4][4];
#pragma unroll
    for (int i = 0; i < 4; ++i)
#pragma unroll
        for (int j = 0; j < 4; ++j)
#pragma unroll
            for (int c = 0; c < 4; ++c) d[i][j][c] = 0.f;

    const int nk = K >> 4;
    float4 ra0, ra1, rw0, rw1;

    // preload kt=0
    ra0 = *reinterpret_cast<const float4*>(A + (size_t)(m0 + row0) * K + kq0 * 4);
    ra1 = *reinterpret_cast<const float4*>(A + (size_t)(m0 + row1) * K + kq1 * 4);
    rw0 = *reinterpret_cast<const float4*>(W + (size_t)(n0 + row0) * K + kq0 * 4);
    rw1 = *reinterpret_cast<const float4*>(W + (size_t)(n0 + row1) * K + kq1 * 4);
    split_store(Ahi, Alo, row0 * GS + kq0 * 4, ra0);
    split_store(Ahi, Alo, row1 * GS + kq1 * 4, ra1);
    split_store(Whi, Wlo, row0 * GS + kq0 * 4, rw0);
    split_store(Whi, Wlo, row1 * GS + kq1 * 4, rw1);
    __syncthreads();

    for (int kt = 0; kt < nk; ++kt) {
        const int buf = kt & 1;
        if (kt + 1 < nk) {
            int kg = (kt + 1) * 16;
            ra0 = *reinterpret_cast<const float4*>(A + (size_t)(m0 + row0) * K + kg + kq0 * 4);
            ra1 = *reinterpret_cast<const float4*>(A + (size_t)(m0 + row1) * K + kg + kq1 * 4);
            rw0 = *reinterpret_cast<const float4*>(W + (size_t)(n0 + row0) * K + kg + kq0 * 4);
            rw1 = *reinterpret_cast<const float4*>(W + (size_t)(n0 + row1) * K + kg + kq1 * 4);
        }

        unsigned aH = sbase + (unsigned)((0 * 2 + buf) * GBUF + aoff) * 2u;
        unsigned aL = sbase + (unsigned)((2 + buf) * GBUF + aoff) * 2u;
        unsigned bH = sbase + (unsigned)((4 + buf) * GBUF + boff) * 2u;
        unsigned bL = sbase + (unsigned)((6 + buf) * GBUF + boff) * 2u;

        unsigned ah[4][4], al[4][4];
#pragma unroll
        for (int i = 0; i < 4; ++i) {
            LDMX4(ah[i][0], ah[i][1], ah[i][2], ah[i][3], aH + i * 16 * GS * 2);
            LDMX4(al[i][0], al[i][1], al[i][2], al[i][3], aL + i * 16 * GS * 2);
        }
#pragma unroll
        for (int j = 0; j < 4; ++j) {
            unsigned bh0, bh1, bl0, bl1;
            LDMX2(bh0, bh1, bH + j * 8 * GS * 2);
            LDMX2(bl0, bl1, bL + j * 8 * GS * 2);
#pragma unroll
            for (int i = 0; i < 4; ++i) {
                MMA_BF16(d[i][j], ah[i], bh0, bh1);   // hi*hi
                MMA_BF16(d[i][j], ah[i], bl0, bl1);   // hi*lo
                MMA_BF16(d[i][j], al[i], bh0, bh1);   // lo*hi
            }
        }

        if (kt + 1 < nk) {
            int nb = (kt + 1) & 1;
            split_store(Ahi + nb * GBUF, Alo + nb * GBUF, row0 * GS + kq0 * 4, ra0);
            split_store(Ahi + nb * GBUF, Alo + nb * GBUF, row1 * GS + kq1 * 4, ra1);
            split_store(Whi + nb * GBUF, Wlo + nb * GBUF, row0 * GS + kq0 * 4, rw0);
            split_store(Whi + nb * GBUF, Wlo + nb * GBUF, row1 * GS + kq1 * 4, rw1);
        }
        __syncthreads();
    }

    // epilogue: D layout c0,c1 -> (row=l/4, col=2*(l%4)+{0,1}); c2,c3 -> row+8
#pragma unroll
    for (int j = 0; j < 4; ++j) {
        int ncol = n0 + wn + j * 8 + 2 * (l & 3);
        float bs0 = bih[ncol] + bhh[ncol];
        float bs1 = bih[ncol + 1] + bhh[ncol + 1];
#pragma unroll
        for (int i = 0; i < 4; ++i) {
            int r = m0 + wm + i * 16 + (l >> 2);
            float2 v0 = {d[i][j][0] + bs0, d[i][j][1] + bs1};
            float2 v1 = {d[i][j][2] + bs0, d[i][j][3] + bs1};
            *reinterpret_cast<float2*>(C + (size_t)r * Gq + ncol) = v0;
            *reinterpret_cast<float2*>(C + (size_t)(r + 8) * Gq + ncol) = v1;
        }
    }
}
#define GEMM_SMEM_BYTES (8 * GBUF * 2)

// ---------------- persistent recurrent scan: 4 groups x 32 CTAs ----------
__global__ void __launch_bounds__(SCAN_TPB) lstm_scan_kernel(
    const float* __restrict__ gx,   // [b][s][2048]
    const float* __restrict__ Whh,  // [2048][512] this layer
    float* __restrict__ out,        // [b][s][512]
    unsigned ebase)
{
    extern __shared__ float sm[];
    float* Wsh  = sm;                      // 64 * WS
    float* hsh  = Wsh + 64 * WS;           // 8 * HP
    float* part = hsh + 8 * HP;            // 8 * 64 * 9
    float* csh  = part + 8 * 64 * 9;       // 128

    const int tid   = threadIdx.x;
    const int cta   = blockIdx.x;
    const int group = cta >> 5;
    const int cidx  = cta & 31;
    const int j0    = cidx * 16;
    const int b0    = group * 8;
    const int wid   = tid >> 5;
    const int lane  = tid & 31;

    if (tid == 0) {
        g_flags[0][cta * 32] = 0u;
        g_flags[1][cta * 32] = 0u;
    }

    for (int i = tid; i < 64 * 128; i += SCAN_TPB) {
        int rl = i >> 7;
        int k4 = i & 127;
        int grow = (rl >> 4) * Hq + j0 + (rl & 15);
        *reinterpret_cast<float4*>(Wsh + rl * WS + k4 * 4) =
            *reinterpret_cast<const float4*>(Whh + (size_t)grow * Hq + k4 * 4);
    }
    if (tid < 128) csh[tid] = 0.f;
    __syncthreads();

    const int bl = tid >> 4;
    const int jj = tid & 15;

    float gxv0 = 0.f, gxv1 = 0.f, gxv2 = 0.f, gxv3 = 0.f;
    if (tid < 128) {
        const float* gp = gx + (size_t)(b0 + bl) * Sq * Gq + j0 + jj;
        gxv0 = gp[0]; gxv1 = gp[Hq]; gxv2 = gp[2 * Hq]; gxv3 = gp[3 * Hq];
    }

    const float* Ws0 = Wsh + lane * WS;
    const float* Ws1 = Wsh + (lane + 32) * WS;
    const int kw = wid * 64;

    for (int t = 0; t < Sq; ++t) {
        const int cur = t & 1, nxt = cur ^ 1;

        if (t > 0) {
            if (wid == 7) {
                unsigned target = ebase + (unsigned)t;
                const unsigned* f = &g_flags[cur][(group * 32 + lane) * 32];
                unsigned seen = 0u;
                do {
                    if (!seen) {
                        unsigned v;
                        asm volatile("ld.relaxed.gpu.global.u32 %0, [%1];"
                                     : "=r"(v) : "l"(f));
                        seen = (v == target) ? 1u : 0u;
                    }
                } while (__all_sync(0xffffffffu, seen) == 0);
            }
            __syncthreads();

            {
                const float4* hsrc =
                    reinterpret_cast<const float4*>(g_h[cur] + (size_t)b0 * Hq);
                int q = tid;
#pragma unroll
                for (int i = 0; i < 4; ++i, q += SCAN_TPB) {
                    int bb = q >> 7;
                    int kq = q & 127;
                    float4 v = __ldcg(hsrc + q);
                    *reinterpret_cast<float4*>(hsh + bb * HP + kq * 4) = v;
                }
            }
            __syncthreads();

            {
                ull acc[2][8];
#pragma unroll
                for (int r = 0; r < 2; ++r)
#pragma unroll
                    for (int b = 0; b < 8; ++b) acc[r][b] = 0ull;
#pragma unroll
                for (int k4 = 0; k4 < 16; ++k4) {
                    int k = kw + k4 * 4;
                    ulonglong2 w0 = *reinterpret_cast<const ulonglong2*>(Ws0 + k);
                    ulonglong2 w1 = *reinterpret_cast<const ulonglong2*>(Ws1 + k);
#pragma unroll
                    for (int b = 0; b < 8; ++b) {
                        ulonglong2 hp =
                            *reinterpret_cast<const ulonglong2*>(hsh + b * HP + k);
                        FMA2(acc[0][b], hp.x, w0.x);
                        FMA2(acc[0][b], hp.y, w0.y);
                        FMA2(acc[1][b], hp.x, w1.x);
                        FMA2(acc[1][b], hp.y, w1.y);
                    }
                }
#pragma unroll
                for (int r = 0; r < 2; ++r)
#pragma unroll
                    for (int b = 0; b < 8; ++b) {
                        float lo, hi; UNPK2(lo, hi, acc[r][b]);
                        part[(wid * 64 + lane + r * 32) * 9 + b] = lo + hi;
                    }
            }
            __syncthreads();
        }

        if (tid < 128) {
            float s0 = 0.f, s1 = 0.f, s2 = 0.f, s3 = 0.f;
            if (t > 0) {
#pragma unroll
                for (int w = 0; w < 8; ++w) {
                    s0 += part[(w * 64 +      jj) * 9 + bl];
                    s1 += part[(w * 64 + 16 + jj) * 9 + bl];
                    s2 += part[(w * 64 + 32 + jj) * 9 + bl];
                    s3 += part[(w * 64 + 48 + jj) * 9 + bl];
                }
            }
            float si = fsigmoid(s0 + gxv0);
            float sf = fsigmoid(s1 + gxv1);
            float tg = ftanh(s2 + gxv2);
            float so = fsigmoid(s3 + gxv3);
            float c  = sf * csh[tid] + si * tg;
            csh[tid] = c;
            float hn = so * ftanh(c);
            int bglob = b0 + bl;
            g_h[nxt][(size_t)bglob * Hq + j0 + jj] = hn;

            asm volatile("bar.sync 1, 128;" ::: "memory");
            if (tid == 0) {
                unsigned val = ebase + (unsigned)(t + 1);
                asm volatile("st.release.gpu.global.u32 [%0], %1;"
                             :: "l"(&g_flags[nxt][cta * 32]), "r"(val) : "memory");
            }

            out[((size_t)bglob * Sq + t) * Hq + j0 + jj] = hn;
            int tn = (t + 1 < Sq) ? t + 1 : t;
            const float* gp = gx + ((size_t)bglob * Sq + tn) * Gq + j0 + jj;
            gxv0 = gp[0]; gxv1 = gp[Hq]; gxv2 = gp[2 * Hq]; gxv3 = gp[3 * Hq];
        }
    }
}

// ---------------- softmax over sequence axis -----------------------------
__global__ void __launch_bounds__(256) softmax_kernel(
    const float* __restrict__ in, float* __restrict__ probs)
{
    int gw = (blockIdx.x * 256 + threadIdx.x) >> 5;
    int lane = threadIdx.x & 31;
    int bb = gw >> 9;
    int hh = gw & 511;
    const float* p = in + (size_t)bb * Sq * Hq + hh;
    float v[8];
    float mx = -3.4e38f;
#pragma unroll
    for (int i = 0; i < 8; ++i) {
        v[i] = p[(size_t)(lane + 32 * i) * Hq];
        mx = fmaxf(mx, v[i]);
    }
#pragma unroll
    for (int o = 16; o; o >>= 1) mx = fmaxf(mx, __shfl_xor_sync(0xffffffffu, mx, o));
    float sum = 0.f;
#pragma unroll
    for (int i = 0; i < 8; ++i) { v[i] = __expf(v[i] - mx); sum += v[i]; }
#pragma unroll
    for (int o = 16; o; o >>= 1) sum += __shfl_xor_sync(0xffffffffu, sum, o);
    float inv = 1.f / sum;
    float* q = probs + (size_t)bb * Sq * Hq + hh;
#pragma unroll
    for (int i = 0; i < 8; ++i) q[(size_t)(lane + 32 * i) * Hq] = v[i] * inv;
}

// ---------------- final FC ------------------------------------------------
__global__ void __launch_bounds__(256) fc_kernel(
    const float* __restrict__ probs, const float* __restrict__ Wfc,
    const float* __restrict__ bfc, float* __restrict__ out)
{
    int gw = (blockIdx.x * 256 + threadIdx.x) >> 5;
    int lane = threadIdx.x & 31;
    const float* p = probs + (size_t)gw * Hq;
    float a0 = 0.f, a1 = 0.f, a2 = 0.f, a3 = 0.f;
    for (int k = lane; k < Hq; k += 32) {
        float pv = p[k];
        a0 += pv * Wfc[k];
        a1 += pv * Wfc[Hq + k];
        a2 += pv * Wfc[2 * Hq + k];
        a3 += pv * Wfc[3 * Hq + k];
    }
#pragma unroll
    for (int o = 16; o; o >>= 1) {
        a0 += __shfl_xor_sync(0xffffffffu, a0, o);
        a1 += __shfl_xor_sync(0xffffffffu, a1, o);
        a2 += __shfl_xor_sync(0xffffffffu, a2, o);
        a3 += __shfl_xor_sync(0xffffffffu, a3, o);
    }
    if (lane == 0) {
        float4 r;
        r.x = a0 + bfc[0]; r.y = a1 + bfc[1];
        r.z = a2 + bfc[2]; r.w = a3 + bfc[3];
        *reinterpret_cast<float4*>(out + (size_t)gw * 4) = r;
    }
}

// ---------------- launcher -----------------------------------------------
extern "C" void kernel_launch(void* const* d_in, const int* in_sizes, int n_in,
                              void* d_out, int out_size)
{
    const float* x    = (const float*)d_in[0];
    const float* Wih0 = (const float*)d_in[1];
    const float* WihR = (const float*)d_in[2];
    const float* Whh  = (const float*)d_in[3];
    const float* bih  = (const float*)d_in[4];
    const float* bhh  = (const float*)d_in[5];
    const float* Wfc  = (const float*)d_in[6];
    const float* bfc  = (const float*)d_in[7];
    float* out = (float*)d_out;

    float *gx, *io0, *io1;
    cudaGetSymbolAddress((void**)&gx,  g_gx);
    cudaGetSymbolAddress((void**)&io0, g_io0);
    cudaGetSymbolAddress((void**)&io1, g_io1);

    cudaFuncSetAttribute(lstm_scan_kernel,
                         cudaFuncAttributeMaxDynamicSharedMemorySize,
                         SCAN_SMEM_BYTES);
    cudaFuncSetAttribute(gemm_kernel,
                         cudaFuncAttributeMaxDynamicSharedMemorySize,
                         GEMM_SMEM_BYTES);

    const float* lin[4]  = {x, io0, io1, io0};
    float*       lout[4] = {io0, io1, io0, io1};

    for (int l = 0; l < 4; ++l) {
        int K = (l == 0) ? Eq : Hq;
        const float* Wih = (l == 0) ? Wih0 : (WihR + (size_t)(l - 1) * Gq * Hq);
        gemm_kernel<<<dim3(Gq / 128, M_TOT / 128), 256, GEMM_SMEM_BYTES>>>(
            lin[l], Wih, bih + (size_t)l * Gq, bhh + (size_t)l * Gq, gx, K);
        lstm_scan_kernel<<<SCAN_NCTA, SCAN_TPB, SCAN_SMEM_BYTES>>>(
            gx, Whh + (size_t)l * Gq * Hq, lout[l], (unsigned)(l * Sq));
    }

    softmax_kernel<<<2048, 256>>>(io1, gx);
    fc_kernel<<<1024, 256>>>(gx, Wfc, bfc, out);
}

// round 10
// speedup vs baseline: 1.2227x; 1.2227x over previous
#include <cuda_runtime.h>
#include <cstdint>

#define Bq 32
#define Sq 256
#define Eq 256
#define Hq 512
#define Gq 2048          // 4*H
#define M_TOT (Bq * Sq)  // 8192

#define SCAN_NCTA 128
#define SCAN_TPB  256
#define HP 132           // hsh row pad (floats)
#define WS 516           // Wsh row stride (floats)

#define SCAN_SMEM_FLOATS (64 * WS + 8 * HP + 8 * 64 * 9 + 128)
#define SCAN_SMEM_BYTES  (SCAN_SMEM_FLOATS * 4)

typedef unsigned long long ull;

#define FMA2(acc, a, b) \
    asm("fma.rn.f32x2 %0, %1, %2, %0;" : "+l"(acc) : "l"(a), "l"(b))
#define DUP2(d, s) \
    asm("mov.b64 %0, {%1, %1};" : "=l"(d) : "f"(s))
#define UNPK2(lo, hi, v) \
    asm("mov.b64 {%0, %1}, %2;" : "=f"(lo), "=f"(hi) : "l"(v))

__device__ __forceinline__ float fsigmoid(float x) {
    return __fdividef(1.f, 1.f + __expf(-x));
}
__device__ __forceinline__ float ftanh(float x) {
    float e = __expf(2.f * x);
    return 1.f - __fdividef(2.f, e + 1.f);
}

// ---------------- device scratch (static, no allocation) ----------------
__device__ float g_gx[M_TOT * Gq];
__device__ float g_io0[M_TOT * Hq];
__device__ float g_io1[M_TOT * Hq];
__device__ float g_h[2][Bq * Hq];
__device__ unsigned g_flags[2][SCAN_NCTA * 32];

// ---------------- input GEMM (FFMA2, double-buffered; R7-proven) ---------
__global__ void __launch_bounds__(256, 2) gemm_kernel(
    const float* __restrict__ A, const float* __restrict__ W,
    const float* __restrict__ bih, const float* __restrict__ bhh,
    float* __restrict__ C, int K)
{
    __shared__ float As[2][8][128];
    __shared__ float Bs[2][8][128];
    const int tid = threadIdx.x;
    const int m0 = blockIdx.y * 128;
    const int n0 = blockIdx.x * 128;
    const int lr = tid >> 1;
    const int lk = (tid & 1) * 4;
    const int tx = tid & 15;
    const int ty = tid >> 4;

    ull acc2[8][4];
#pragma unroll
    for (int i = 0; i < 8; ++i)
#pragma unroll
        for (int j = 0; j < 4; ++j) acc2[i][j] = 0ull;

    const float* Ap = A + (size_t)(m0 + lr) * K + lk;
    const float* Wp = W + (size_t)(n0 + lr) * K + lk;
    float4 pa = *reinterpret_cast<const float4*>(Ap);
    float4 pb = *reinterpret_cast<const float4*>(Wp);

    As[0][lk + 0][lr] = pa.x; As[0][lk + 1][lr] = pa.y;
    As[0][lk + 2][lr] = pa.z; As[0][lk + 3][lr] = pa.w;
    Bs[0][lk + 0][lr] = pb.x; Bs[0][lk + 1][lr] = pb.y;
    Bs[0][lk + 2][lr] = pb.z; Bs[0][lk + 3][lr] = pb.w;
    __syncthreads();

    const int nk = K >> 3;
    for (int kt = 0; kt < nk; ++kt) {
        const int buf = kt & 1;
        if (kt + 1 < nk) {
            pa = *reinterpret_cast<const float4*>(Ap + (kt + 1) * 8);
            pb = *reinterpret_cast<const float4*>(Wp + (kt + 1) * 8);
        }
#pragma unroll
        for (int kk = 0; kk < 8; ++kk) {
            float4 a0 = *reinterpret_cast<const float4*>(&As[buf][kk][ty * 4]);
            float4 a1 = *reinterpret_cast<const float4*>(&As[buf][kk][64 + ty * 4]);
            ulonglong2 bb0 = *reinterpret_cast<const ulonglong2*>(&Bs[buf][kk][tx * 4]);
            ulonglong2 bb1 = *reinterpret_cast<const ulonglong2*>(&Bs[buf][kk][64 + tx * 4]);
            float am[8] = {a0.x, a0.y, a0.z, a0.w, a1.x, a1.y, a1.z, a1.w};
            ull bp0 = bb0.x, bp1 = bb0.y, bp2 = bb1.x, bp3 = bb1.y;
#pragma unroll
            for (int i = 0; i < 8; ++i) {
                ull a2; DUP2(a2, am[i]);
                FMA2(acc2[i][0], a2, bp0);
                FMA2(acc2[i][1], a2, bp1);
                FMA2(acc2[i][2], a2, bp2);
                FMA2(acc2[i][3], a2, bp3);
            }
        }
        if (kt + 1 < nk) {
            const int nb = buf ^ 1;
            As[nb][lk + 0][lr] = pa.x; As[nb][lk + 1][lr] = pa.y;
            As[nb][lk + 2][lr] = pa.z; As[nb][lk + 3][lr] = pa.w;
            Bs[nb][lk + 0][lr] = pb.x; Bs[nb][lk + 1][lr] = pb.y;
            Bs[nb][lk + 2][lr] = pb.z; Bs[nb][lk + 3][lr] = pb.w;
            __syncthreads();
        }
    }

    float acc[8][8];
#pragma unroll
    for (int i = 0; i < 8; ++i)
#pragma unroll
        for (int j = 0; j < 4; ++j)
            UNPK2(acc[i][2 * j], acc[i][2 * j + 1], acc2[i][j]);

    const int nc0 = n0 + tx * 4;
    const int nc1 = n0 + 64 + tx * 4;
    float bs0[4], bs1[4];
#pragma unroll
    for (int j = 0; j < 4; ++j) {
        bs0[j] = bih[nc0 + j] + bhh[nc0 + j];
        bs1[j] = bih[nc1 + j] + bhh[nc1 + j];
    }
#pragma unroll
    for (int i = 0; i < 8; ++i) {
        int m = m0 + ((i < 4) ? (ty * 4 + i) : (64 + ty * 4 + i - 4));
        float4 v0, v1;
        v0.x = acc[i][0] + bs0[0]; v0.y = acc[i][1] + bs0[1];
        v0.z = acc[i][2] + bs0[2]; v0.w = acc[i][3] + bs0[3];
        v1.x = acc[i][4] + bs1[0]; v1.y = acc[i][5] + bs1[1];
        v1.z = acc[i][6] + bs1[2]; v1.w = acc[i][7] + bs1[3];
        *reinterpret_cast<float4*>(C + (size_t)m * Gq + nc0) = v0;
        *reinterpret_cast<float4*>(C + (size_t)m * Gq + nc1) = v1;
    }
}

// ---------------- persistent recurrent scan: 4 groups x 32 CTAs ----------
// Warp-autonomous wait+stage: each warp polls the group flags and stages its
// own 64-k chunk of h (private hsh columns); only one CTA-wide sync per step.
__global__ void __launch_bounds__(SCAN_TPB) lstm_scan_kernel(
    const float* __restrict__ gx,   // [b][s][2048]
    const float* __restrict__ Whh,  // [2048][512] this layer
    float* __restrict__ out,        // [b][s][512]
    unsigned ebase)
{
    extern __shared__ float sm[];
    float* Wsh  = sm;                      // 64 * WS
    float* hsh  = Wsh + 64 * WS;           // 8 * HP
    float* part = hsh + 8 * HP;            // 8 * 64 * 9
    float* csh  = part + 8 * 64 * 9;       // 128

    const int tid   = threadIdx.x;
    const int cta   = blockIdx.x;
    const int group = cta >> 5;
    const int cidx  = cta & 31;
    const int j0    = cidx * 16;
    const int b0    = group * 8;
    const int wid   = tid >> 5;
    const int lane  = tid & 31;

    if (tid == 0) {
        g_flags[0][cta * 32] = 0u;
        g_flags[1][cta * 32] = 0u;
    }

    for (int i = tid; i < 64 * 128; i += SCAN_TPB) {
        int rl = i >> 7;
        int k4 = i & 127;
        int grow = (rl >> 4) * Hq + j0 + (rl & 15);
        *reinterpret_cast<float4*>(Wsh + rl * WS + k4 * 4) =
            *reinterpret_cast<const float4*>(Whh + (size_t)grow * Hq + k4 * 4);
    }
    if (tid < 128) csh[tid] = 0.f;
    __syncthreads();

    const int bl = tid >> 4;           // gate-thread local batch (tid<128)
    const int jj = tid & 15;           // gate-thread h-col

    float gxv0 = 0.f, gxv1 = 0.f, gxv2 = 0.f, gxv3 = 0.f;
    if (tid < 128) {
        const float* gp = gx + (size_t)(b0 + bl) * Sq * Gq + j0 + jj;
        gxv0 = gp[0]; gxv1 = gp[Hq]; gxv2 = gp[2 * Hq]; gxv3 = gp[3 * Hq];
    }

    const float* Ws0 = Wsh + lane * WS;
    const float* Ws1 = Wsh + (lane + 32) * WS;
    const int kw = wid * 64;
    const int sj = lane & 15;          // stage: float4 pos within k-chunk
    const int sb = lane >> 4;          // stage: b parity

    for (int t = 0; t < Sq; ++t) {
        const int cur = t & 1, nxt = cur ^ 1;

        if (t > 0) {
            // ---- wait: EVERY warp polls the group's 32 flags ----
            {
                unsigned target = ebase + (unsigned)t;
                const unsigned* f = &g_flags[cur][(group * 32 + lane) * 32];
                unsigned seen = 0u;
                do {
                    if (!seen) {
                        unsigned v;
                        asm volatile("ld.relaxed.gpu.global.u32 %0, [%1];"
                                     : "=r"(v) : "l"(f));
                        seen = (v == target) ? 1u : 0u;
                    }
                } while (__all_sync(0xffffffffu, seen) == 0);
            }

            // ---- stage OWN k-chunk: hsh[b][kw..kw+64) for b=0..7 ----
            {
                const float* hbase = g_h[cur] + (size_t)b0 * Hq + kw;
#pragma unroll
                for (int p = 0; p < 4; ++p) {
                    int b = sb + p * 2;
                    float4 v = __ldcg(reinterpret_cast<const float4*>(
                                          hbase + (size_t)b * Hq) + sj);
                    *reinterpret_cast<float4*>(hsh + b * HP + kw + sj * 4) = v;
                }
            }
            __syncwarp();

            // ---- dot: warp wid -> k chunk [kw,kw+64); lane rows (lane,lane+32)
            {
                ull acc[2][8];
#pragma unroll
                for (int r = 0; r < 2; ++r)
#pragma unroll
                    for (int b = 0; b < 8; ++b) acc[r][b] = 0ull;
#pragma unroll
                for (int k4 = 0; k4 < 16; ++k4) {
                    int k = kw + k4 * 4;
                    ulonglong2 w0 = *reinterpret_cast<const ulonglong2*>(Ws0 + k);
                    ulonglong2 w1 = *reinterpret_cast<const ulonglong2*>(Ws1 + k);
#pragma unroll
                    for (int b = 0; b < 8; ++b) {
                        ulonglong2 hp =
                            *reinterpret_cast<const ulonglong2*>(hsh + b * HP + k);
                        FMA2(acc[0][b], hp.x, w0.x);
                        FMA2(acc[0][b], hp.y, w0.y);
                        FMA2(acc[1][b], hp.x, w1.x);
                        FMA2(acc[1][b], hp.y, w1.y);
                    }
                }
#pragma unroll
                for (int r = 0; r < 2; ++r)
#pragma unroll
                    for (int b = 0; b < 8; ++b) {
                        float lo, hi; UNPK2(lo, hi, acc[r][b]);
                        part[(wid * 64 + lane + r * 32) * 9 + b] = lo + hi;
                    }
            }
            __syncthreads();   // partials visible to gate threads
        }

        // ---- gates (threads 0..127), early publish ----
        if (tid < 128) {
            float s0 = 0.f, s1 = 0.f, s2 = 0.f, s3 = 0.f;
            if (t > 0) {
#pragma unroll
                for (int w = 0; w < 8; ++w) {
                    s0 += part[(w * 64 +      jj) * 9 + bl];
                    s1 += part[(w * 64 + 16 + jj) * 9 + bl];
                    s2 += part[(w * 64 + 32 + jj) * 9 + bl];
                    s3 += part[(w * 64 + 48 + jj) * 9 + bl];
                }
            }
            float si = fsigmoid(s0 + gxv0);
            float sf = fsigmoid(s1 + gxv1);
            float tg = ftanh(s2 + gxv2);
            float so = fsigmoid(s3 + gxv3);
            float c  = sf * csh[tid] + si * tg;
            csh[tid] = c;
            float hn = so * ftanh(c);
            int bglob = b0 + bl;
            g_h[nxt][(size_t)bglob * Hq + j0 + jj] = hn;

            asm volatile("bar.sync 1, 128;" ::: "memory");   // gate warps only
            if (tid == 0) {
                unsigned val = ebase + (unsigned)(t + 1);
                asm volatile("membar.gl;" ::: "memory");
                asm volatile("st.release.gpu.global.u32 [%0], %1;"
                             :: "l"(&g_flags[nxt][cta * 32]), "r"(val) : "memory");
            }

            // off critical path
            out[((size_t)bglob * Sq + t) * Hq + j0 + jj] = hn;
            int tn = (t + 1 < Sq) ? t + 1 : t;
            const float* gp = gx + ((size_t)bglob * Sq + tn) * Gq + j0 + jj;
            gxv0 = gp[0]; gxv1 = gp[Hq]; gxv2 = gp[2 * Hq]; gxv3 = gp[3 * Hq];
        }
        // no trailing sync: poll(t+1) on OWN flag orders part reuse
    }
}

// ---------------- softmax over sequence axis -----------------------------
__global__ void __launch_bounds__(256) softmax_kernel(
    const float* __restrict__ in, float* __restrict__ probs)
{
    int gw = (blockIdx.x * 256 + threadIdx.x) >> 5;
    int lane = threadIdx.x & 31;
    int bb = gw >> 9;
    int hh = gw & 511;
    const float* p = in + (size_t)bb * Sq * Hq + hh;
    float v[8];
    float mx = -3.4e38f;
#pragma unroll
    for (int i = 0; i < 8; ++i) {
        v[i] = p[(size_t)(lane + 32 * i) * Hq];
        mx = fmaxf(mx, v[i]);
    }
#pragma unroll
    for (int o = 16; o; o >>= 1) mx = fmaxf(mx, __shfl_xor_sync(0xffffffffu, mx, o));
    float sum = 0.f;
#pragma unroll
    for (int i = 0; i < 8; ++i) { v[i] = __expf(v[i] - mx); sum += v[i]; }
#pragma unroll
    for (int o = 16; o; o >>= 1) sum += __shfl_xor_sync(0xffffffffu, sum, o);
    float inv = 1.f / sum;
    float* q = probs + (size_t)bb * Sq * Hq + hh;
#pragma unroll
    for (int i = 0; i < 8; ++i) q[(size_t)(lane + 32 * i) * Hq] = v[i] * inv;
}

// ---------------- final FC ------------------------------------------------
__global__ void __launch_bounds__(256) fc_kernel(
    const float* __restrict__ probs, const float* __restrict__ Wfc,
    const float* __restrict__ bfc, float* __restrict__ out)
{
    int gw = (blockIdx.x * 256 + threadIdx.x) >> 5;
    int lane = threadIdx.x & 31;
    const float* p = probs + (size_t)gw * Hq;
    float a0 = 0.f, a1 = 0.f, a2 = 0.f, a3 = 0.f;
    for (int k = lane; k < Hq; k += 32) {
        float pv = p[k];
        a0 += pv * Wfc[k];
        a1 += pv * Wfc[Hq + k];
        a2 += pv * Wfc[2 * Hq + k];
        a3 += pv * Wfc[3 * Hq + k];
    }
#pragma unroll
    for (int o = 16; o; o >>= 1) {
        a0 += __shfl_xor_sync(0xffffffffu, a0, o);
        a1 += __shfl_xor_sync(0xffffffffu, a1, o);
        a2 += __shfl_xor_sync(0xffffffffu, a2, o);
        a3 += __shfl_xor_sync(0xffffffffu, a3, o);
    }
    if (lane == 0) {
        float4 r;
        r.x = a0 + bfc[0]; r.y = a1 + bfc[1];
        r.z = a2 + bfc[2]; r.w = a3 + bfc[3];
        *reinterpret_cast<float4*>(out + (size_t)gw * 4) = r;
    }
}

// ---------------- launcher -----------------------------------------------
extern "C" void kernel_launch(void* const* d_in, const int* in_sizes, int n_in,
                              void* d_out, int out_size)
{
    const float* x    = (const float*)d_in[0];
    const float* Wih0 = (const float*)d_in[1];
    const float* WihR = (const float*)d_in[2];
    const float* Whh  = (const float*)d_in[3];
    const float* bih  = (const float*)d_in[4];
    const float* bhh  = (const float*)d_in[5];
    const float* Wfc  = (const float*)d_in[6];
    const float* bfc  = (const float*)d_in[7];
    float* out = (float*)d_out;

    float *gx, *io0, *io1;
    cudaGetSymbolAddress((void**)&gx,  g_gx);
    cudaGetSymbolAddress((void**)&io0, g_io0);
    cudaGetSymbolAddress((void**)&io1, g_io1);

    cudaFuncSetAttribute(lstm_scan_kernel,
                         cudaFuncAttributeMaxDynamicSharedMemorySize,
                         SCAN_SMEM_BYTES);

    const float* lin[4]  = {x, io0, io1, io0};
    float*       lout[4] = {io0, io1, io0, io1};

    for (int l = 0; l < 4; ++l) {
        int K = (l == 0) ? Eq : Hq;
        const float* Wih = (l == 0) ? Wih0 : (WihR + (size_t)(l - 1) * Gq * Hq);
        gemm_kernel<<<dim3(Gq / 128, M_TOT / 128), 256>>>(
            lin[l], Wih, bih + (size_t)l * Gq, bhh + (size_t)l * Gq, gx, K);
        lstm_scan_kernel<<<SCAN_NCTA, SCAN_TPB, SCAN_SMEM_BYTES>>>(
            gx, Whh + (size_t)l * Gq * Hq, lout[l], (unsigned)(l * Sq));
    }

    softmax_kernel<<<2048, 256>>>(io1, gx);
    fc_kernel<<<1024, 256>>>(gx, Wfc, bfc, out);
}